// round 2
// baseline (speedup 1.0000x reference)
#include <cuda_runtime.h>
#include <math.h>

#define N_NODES 100000
#define IN_CH 128
#define HID 256
#define EMB 128
#define N_PAIRS 500000

// scratch for node embeddings z (51.2 MB) — static device array (no allocs allowed)
__device__ float g_z[(size_t)N_NODES * EMB];

__device__ __forceinline__ float4 ld4(const float* p) { return *reinterpret_cast<const float4*>(p); }
__device__ __forceinline__ void st4(float* p, float4 v) { *reinterpret_cast<float4*>(p) = v; }

// ---------------------------------------------------------------------------
// Node kernel: 64 nodes/block, 256 threads.
//   phase 0: load+normalize x tile into smem (64x128)
//   phase 1: h = xf@W1 + b1, BN, relu  -> smem (64x256). Thread tile 16x4.
//   phase 2: z = relu(h@W2 + b2)       -> g_z.           Thread tile 8x4.
// ---------------------------------------------------------------------------
__global__ __launch_bounds__(256) void node_kernel(
    const float* __restrict__ x, const float* __restrict__ xm, const float* __restrict__ xsd,
    const float* __restrict__ W1, const float* __restrict__ b1,
    const float* __restrict__ bng, const float* __restrict__ bnb,
    const float* __restrict__ bnm, const float* __restrict__ bnv,
    const float* __restrict__ W2, const float* __restrict__ b2)
{
    extern __shared__ float sm[];
    float* xs = sm;                 // 64 x 128
    float* hs = sm + 64 * IN_CH;    // 64 x 256
    const int t = threadIdx.x;
    const int nb0 = blockIdx.x * 64;

    // phase 0: load + nan_to_num + standardize + clip
    for (int i = t; i < 64 * (IN_CH / 4); i += 256) {
        int n = i >> 5, c4 = i & 31;
        int node = nb0 + n;
        float4 v = make_float4(0.f, 0.f, 0.f, 0.f);
        if (node < N_NODES) v = ld4(x + (size_t)node * IN_CH + 4 * c4);
        float4 m = ld4(xm + 4 * c4), s = ld4(xsd + 4 * c4);
        float4 o;
        float a;
        a = isfinite(v.x) ? v.x : 0.f; a = (a - m.x) / s.x; o.x = fminf(fmaxf(a, -10.f), 10.f);
        a = isfinite(v.y) ? v.y : 0.f; a = (a - m.y) / s.y; o.y = fminf(fmaxf(a, -10.f), 10.f);
        a = isfinite(v.z) ? v.z : 0.f; a = (a - m.z) / s.z; o.z = fminf(fmaxf(a, -10.f), 10.f);
        a = isfinite(v.w) ? v.w : 0.f; a = (a - m.w) / s.w; o.w = fminf(fmaxf(a, -10.f), 10.f);
        st4(xs + n * IN_CH + 4 * c4, o);
    }
    __syncthreads();

    // phase 1: GEMM 128 -> 256, fused bias + BN + relu
    {
        const int cg = t & 63;   // 64 col-groups of 4 -> 256 cols
        const int ng = t >> 6;   // 4 node-groups of 16
        float acc[16][4];
        #pragma unroll
        for (int p = 0; p < 16; p++) { acc[p][0] = acc[p][1] = acc[p][2] = acc[p][3] = 0.f; }
        const float* xrow = xs + ng * 16 * IN_CH;
        #pragma unroll 4
        for (int k = 0; k < IN_CH; k++) {
            float4 w = ld4(W1 + k * HID + 4 * cg);
            #pragma unroll
            for (int p = 0; p < 16; p++) {
                float a = xrow[p * IN_CH + k];
                acc[p][0] += a * w.x; acc[p][1] += a * w.y;
                acc[p][2] += a * w.z; acc[p][3] += a * w.w;
            }
        }
        float4 bb = ld4(b1 + 4 * cg), gg = ld4(bng + 4 * cg), be = ld4(bnb + 4 * cg);
        float4 mm = ld4(bnm + 4 * cg), vv = ld4(bnv + 4 * cg);
        float4 sc, off;
        sc.x = gg.x * rsqrtf(vv.x + 1e-5f); off.x = be.x + (bb.x - mm.x) * sc.x;
        sc.y = gg.y * rsqrtf(vv.y + 1e-5f); off.y = be.y + (bb.y - mm.y) * sc.y;
        sc.z = gg.z * rsqrtf(vv.z + 1e-5f); off.z = be.z + (bb.z - mm.z) * sc.z;
        sc.w = gg.w * rsqrtf(vv.w + 1e-5f); off.w = be.w + (bb.w - mm.w) * sc.w;
        #pragma unroll
        for (int p = 0; p < 16; p++) {
            float4 h;
            h.x = fmaxf(acc[p][0] * sc.x + off.x, 0.f);
            h.y = fmaxf(acc[p][1] * sc.y + off.y, 0.f);
            h.z = fmaxf(acc[p][2] * sc.z + off.z, 0.f);
            h.w = fmaxf(acc[p][3] * sc.w + off.w, 0.f);
            st4(hs + (ng * 16 + p) * HID + 4 * cg, h);
        }
    }
    __syncthreads();

    // phase 2: GEMM 256 -> 128, fused bias + relu, write z
    {
        const int cg = t & 31;   // 32 col-groups of 4 -> 128 cols
        const int ng = t >> 5;   // 8 node-groups of 8
        float acc[8][4];
        #pragma unroll
        for (int p = 0; p < 8; p++) { acc[p][0] = acc[p][1] = acc[p][2] = acc[p][3] = 0.f; }
        const float* hrow = hs + ng * 8 * HID;
        #pragma unroll 4
        for (int k = 0; k < HID; k++) {
            float4 w = ld4(W2 + k * EMB + 4 * cg);
            #pragma unroll
            for (int p = 0; p < 8; p++) {
                float a = hrow[p * HID + k];
                acc[p][0] += a * w.x; acc[p][1] += a * w.y;
                acc[p][2] += a * w.z; acc[p][3] += a * w.w;
            }
        }
        float4 bb = ld4(b2 + 4 * cg);
        #pragma unroll
        for (int p = 0; p < 8; p++) {
            int node = nb0 + ng * 8 + p;
            if (node < N_NODES) {
                float4 r;
                r.x = fmaxf(acc[p][0] + bb.x, 0.f);
                r.y = fmaxf(acc[p][1] + bb.y, 0.f);
                r.z = fmaxf(acc[p][2] + bb.z, 0.f);
                r.w = fmaxf(acc[p][3] + bb.w, 0.f);
                st4(g_z + (size_t)node * EMB + 4 * cg, r);
            }
        }
    }
}

// ---------------------------------------------------------------------------
// Pair kernel: 64 pairs/block, 256 threads.
//   gather src/dst embeddings into smem (2 x 64x128)
//   GEMM1 514 -> 256 (feature segments computed on the fly), relu -> smem s1
//   GEMM2 256 -> 128, relu
//   GEMM3 128 -> 1 via warp reduction, nan_to_num, write logits
// edge_pairs is int32 (JAX coerces int64 -> int32 without x64 mode).
// ---------------------------------------------------------------------------
__global__ __launch_bounds__(256) void pair_kernel(
    const int* __restrict__ ep, const float* __restrict__ ldeg,
    const float* __restrict__ SW1, const float* __restrict__ Sb1,
    const float* __restrict__ SW2, const float* __restrict__ Sb2,
    const float* __restrict__ SW3, const float* __restrict__ Sb3,
    float* __restrict__ out)
{
    extern __shared__ float sm[];   // 64*256 floats (phase A: srcs|dsts, phase B: s1)
    __shared__ int sidx[64], didx[64];
    __shared__ float sdeg[64], ddeg[64];
    float* srcs = sm;               // 64 x 128
    float* dsts = sm + 64 * EMB;    // 64 x 128
    const int t = threadIdx.x;
    const int p0 = blockIdx.x * 64;

    if (t < 64) {
        int p = p0 + t;
        int si = 0, di = 0;
        float a = 0.f, b = 0.f;
        if (p < N_PAIRS) {
            si = ep[2 * (size_t)p];
            di = ep[2 * (size_t)p + 1];
            a = ldeg[si]; b = ldeg[di];
        }
        sidx[t] = si; didx[t] = di;
        sdeg[t] = a; ddeg[t] = b;
    }
    __syncthreads();

    // gather embeddings (z resident in L2)
    for (int i = t; i < 64 * 32; i += 256) {
        int pp = i >> 5, c4 = i & 31;
        st4(srcs + pp * EMB + 4 * c4, ld4(g_z + (size_t)sidx[pp] * EMB + 4 * c4));
        st4(dsts + pp * EMB + 4 * c4, ld4(g_z + (size_t)didx[pp] * EMB + 4 * c4));
    }
    __syncthreads();

    // GEMM1: [64 x 514] @ [514 x 256]
    const int cg = t & 63;   // cols 4*cg
    const int pg = t >> 6;   // pairs pg*16 ..
    float acc[16][4];
    #pragma unroll
    for (int p = 0; p < 16; p++) { acc[p][0] = acc[p][1] = acc[p][2] = acc[p][3] = 0.f; }
    const float* srow = srcs + pg * 16 * EMB;
    const float* drow = dsts + pg * 16 * EMB;

    #pragma unroll 4
    for (int k = 0; k < EMB; k++) {                     // seg 0: src
        float4 w = ld4(SW1 + k * HID + 4 * cg);
        #pragma unroll
        for (int p = 0; p < 16; p++) {
            float a = srow[p * EMB + k];
            acc[p][0] += a * w.x; acc[p][1] += a * w.y;
            acc[p][2] += a * w.z; acc[p][3] += a * w.w;
        }
    }
    #pragma unroll 4
    for (int k = 0; k < EMB; k++) {                     // seg 1: dst
        float4 w = ld4(SW1 + (EMB + k) * HID + 4 * cg);
        #pragma unroll
        for (int p = 0; p < 16; p++) {
            float a = drow[p * EMB + k];
            acc[p][0] += a * w.x; acc[p][1] += a * w.y;
            acc[p][2] += a * w.z; acc[p][3] += a * w.w;
        }
    }
    #pragma unroll 2
    for (int k = 0; k < EMB; k++) {                     // seg 2: src*dst
        float4 w = ld4(SW1 + (2 * EMB + k) * HID + 4 * cg);
        #pragma unroll
        for (int p = 0; p < 16; p++) {
            float a = srow[p * EMB + k] * drow[p * EMB + k];
            acc[p][0] += a * w.x; acc[p][1] += a * w.y;
            acc[p][2] += a * w.z; acc[p][3] += a * w.w;
        }
    }
    #pragma unroll 2
    for (int k = 0; k < EMB; k++) {                     // seg 3: |src-dst|
        float4 w = ld4(SW1 + (3 * EMB + k) * HID + 4 * cg);
        #pragma unroll
        for (int p = 0; p < 16; p++) {
            float a = fabsf(srow[p * EMB + k] - drow[p * EMB + k]);
            acc[p][0] += a * w.x; acc[p][1] += a * w.y;
            acc[p][2] += a * w.z; acc[p][3] += a * w.w;
        }
    }
    {                                                   // seg 4: degrees (k=512,513)
        float4 wa = ld4(SW1 + 512 * HID + 4 * cg);
        float4 wb = ld4(SW1 + 513 * HID + 4 * cg);
        #pragma unroll
        for (int p = 0; p < 16; p++) {
            float a = sdeg[pg * 16 + p], b = ddeg[pg * 16 + p];
            acc[p][0] += a * wa.x + b * wb.x;
            acc[p][1] += a * wa.y + b * wb.y;
            acc[p][2] += a * wa.z + b * wb.z;
            acc[p][3] += a * wa.w + b * wb.w;
        }
    }
    float4 bb1 = ld4(Sb1 + 4 * cg);
    __syncthreads();   // all srcs/dsts reads complete before overwrite
    float* s1 = sm;    // 64 x 256 overlay
    #pragma unroll
    for (int p = 0; p < 16; p++) {
        float4 r;
        r.x = fmaxf(acc[p][0] + bb1.x, 0.f);
        r.y = fmaxf(acc[p][1] + bb1.y, 0.f);
        r.z = fmaxf(acc[p][2] + bb1.z, 0.f);
        r.w = fmaxf(acc[p][3] + bb1.w, 0.f);
        st4(s1 + (pg * 16 + p) * HID + 4 * cg, r);
    }
    __syncthreads();

    // GEMM2: [64 x 256] @ [256 x 128]
    const int cg2 = t & 31;  // cols 4*cg2
    const int pg2 = t >> 5;  // pairs pg2*8 ..
    float acc2[8][4];
    #pragma unroll
    for (int p = 0; p < 8; p++) { acc2[p][0] = acc2[p][1] = acc2[p][2] = acc2[p][3] = 0.f; }
    const float* s1row = s1 + pg2 * 8 * HID;
    #pragma unroll 4
    for (int k = 0; k < HID; k++) {
        float4 w = ld4(SW2 + k * EMB + 4 * cg2);
        #pragma unroll
        for (int p = 0; p < 8; p++) {
            float a = s1row[p * HID + k];
            acc2[p][0] += a * w.x; acc2[p][1] += a * w.y;
            acc2[p][2] += a * w.z; acc2[p][3] += a * w.w;
        }
    }
    float4 bb2 = ld4(Sb2 + 4 * cg2);
    float4 w3 = ld4(SW3 + 4 * cg2);

    // GEMM3: relu(s2) . SW3, reduced across the warp (lanes = 32 col-groups)
    float r[8];
    #pragma unroll
    for (int p = 0; p < 8; p++) {
        float v0 = fmaxf(acc2[p][0] + bb2.x, 0.f);
        float v1 = fmaxf(acc2[p][1] + bb2.y, 0.f);
        float v2 = fmaxf(acc2[p][2] + bb2.z, 0.f);
        float v3 = fmaxf(acc2[p][3] + bb2.w, 0.f);
        r[p] = v0 * w3.x + v1 * w3.y + v2 * w3.z + v3 * w3.w;
    }
    #pragma unroll
    for (int off = 16; off > 0; off >>= 1) {
        #pragma unroll
        for (int p = 0; p < 8; p++)
            r[p] += __shfl_xor_sync(0xffffffffu, r[p], off);
    }
    if ((t & 31) == 0) {
        float sb = Sb3[0];
        #pragma unroll
        for (int p = 0; p < 8; p++) {
            int pr = p0 + pg2 * 8 + p;
            if (pr < N_PAIRS) {
                float l = r[p] + sb;
                if (isnan(l)) l = 0.f;
                else if (isinf(l)) l = (l > 0.f) ? 20.f : -20.f;
                out[pr] = l;
            }
        }
    }
}

extern "C" void kernel_launch(void* const* d_in, const int* in_sizes, int n_in,
                              void* d_out, int out_size)
{
    const float* x    = (const float*)d_in[0];
    // d_in[1] = edge_index (unused by reference)
    const int*   ep   = (const int*)d_in[2];      // int32 (JAX default, no x64)
    const float* xm   = (const float*)d_in[3];
    const float* xsd  = (const float*)d_in[4];
    const float* ldeg = (const float*)d_in[5];
    const float* W1   = (const float*)d_in[6];
    const float* b1   = (const float*)d_in[7];
    const float* bng  = (const float*)d_in[8];
    const float* bnb  = (const float*)d_in[9];
    const float* bnm  = (const float*)d_in[10];
    const float* bnv  = (const float*)d_in[11];
    const float* W2   = (const float*)d_in[12];
    const float* b2   = (const float*)d_in[13];
    const float* SW1  = (const float*)d_in[14];
    const float* Sb1  = (const float*)d_in[15];
    const float* SW2  = (const float*)d_in[16];
    const float* Sb2  = (const float*)d_in[17];
    const float* SW3  = (const float*)d_in[18];
    const float* Sb3  = (const float*)d_in[19];
    float* out = (float*)d_out;

    cudaFuncSetAttribute(node_kernel, cudaFuncAttributeMaxDynamicSharedMemorySize, 98304);
    cudaFuncSetAttribute(pair_kernel, cudaFuncAttributeMaxDynamicSharedMemorySize, 65536);

    node_kernel<<<(N_NODES + 63) / 64, 256, 98304>>>(x, xm, xsd, W1, b1, bng, bnb, bnm, bnv, W2, b2);
    pair_kernel<<<(N_PAIRS + 63) / 64, 256, 65536>>>(ep, ldeg, SW1, Sb1, SW2, Sb2, SW3, Sb3, out);
}

// round 3
// speedup vs baseline: 1.4142x; 1.4142x over previous
#include <cuda_runtime.h>
#include <math.h>

#define N_NODES 100000
#define IN_CH 128
#define HID 256
#define EMB 128
#define N_PAIRS 500000

// scratch for node embeddings z (51.2 MB) — static device array (no allocs allowed)
__device__ float g_z[(size_t)N_NODES * EMB];

__device__ __forceinline__ float4 ld4(const float* p) { return *reinterpret_cast<const float4*>(p); }
__device__ __forceinline__ void st4(float* p, float4 v) { *reinterpret_cast<float4*>(p) = v; }

// ---------------------------------------------------------------------------
// Node kernel: 64 nodes/block, 256 threads, 2 CTAs/SM.
//   phase 0: load+normalize x tile into smem TRANSPOSED [128 ch][64 nodes]
//   phase 1: h = xf@W1 + b1, BN, relu  -> smem hs [64][256]. Tile 16x4.
//   phase 2: z = relu(h@W2 + b2)       -> g_z.              Tile 8x4.
// ---------------------------------------------------------------------------
__global__ __launch_bounds__(256, 2) void node_kernel(
    const float* __restrict__ x, const float* __restrict__ xm, const float* __restrict__ xsd,
    const float* __restrict__ W1, const float* __restrict__ b1,
    const float* __restrict__ bng, const float* __restrict__ bnb,
    const float* __restrict__ bnm, const float* __restrict__ bnv,
    const float* __restrict__ W2, const float* __restrict__ b2)
{
    extern __shared__ float sm[];
    float* xsT = sm;                 // [128 ch][64 nodes]
    float* hs  = sm + IN_CH * 64;    // [64 nodes][256]
    const int t = threadIdx.x;
    const int nb0 = blockIdx.x * 64;

    // phase 0: load + nan_to_num + standardize + clip, store transposed
    // lane = node -> conflict-free scalar STS
    {
        const int nn = t & 63;
        const int node = nb0 + nn;
        const bool ok = node < N_NODES;
        #pragma unroll
        for (int it = 0; it < 8; it++) {
            int c4 = (t >> 6) + 4 * it;   // 0..31
            float4 v = make_float4(0.f, 0.f, 0.f, 0.f);
            if (ok) v = ld4(x + (size_t)node * IN_CH + 4 * c4);
            float4 m = ld4(xm + 4 * c4), s = ld4(xsd + 4 * c4);
            float a;
            a = isfinite(v.x) ? v.x : 0.f; a = (a - m.x) / s.x; xsT[(4*c4+0)*64+nn] = fminf(fmaxf(a,-10.f),10.f);
            a = isfinite(v.y) ? v.y : 0.f; a = (a - m.y) / s.y; xsT[(4*c4+1)*64+nn] = fminf(fmaxf(a,-10.f),10.f);
            a = isfinite(v.z) ? v.z : 0.f; a = (a - m.z) / s.z; xsT[(4*c4+2)*64+nn] = fminf(fmaxf(a,-10.f),10.f);
            a = isfinite(v.w) ? v.w : 0.f; a = (a - m.w) / s.w; xsT[(4*c4+3)*64+nn] = fminf(fmaxf(a,-10.f),10.f);
        }
    }
    __syncthreads();

    // phase 1: GEMM 128 -> 256, fused bias + BN + relu
    {
        const int cg = t & 63;   // 64 col-groups of 4 -> 256 cols
        const int ng = t >> 6;   // 4 node-groups of 16
        float acc[16][4];
        #pragma unroll
        for (int p = 0; p < 16; p++) { acc[p][0] = acc[p][1] = acc[p][2] = acc[p][3] = 0.f; }
        const float* xcol = xsT + ng * 16;
        #pragma unroll 2
        for (int k = 0; k < IN_CH; k++) {
            float a[16];
            #pragma unroll
            for (int q = 0; q < 4; q++) {
                float4 v = ld4(xcol + k * 64 + 4 * q);
                a[4*q] = v.x; a[4*q+1] = v.y; a[4*q+2] = v.z; a[4*q+3] = v.w;
            }
            float4 w = ld4(W1 + k * HID + 4 * cg);
            #pragma unroll
            for (int p = 0; p < 16; p++) {
                acc[p][0] += a[p] * w.x; acc[p][1] += a[p] * w.y;
                acc[p][2] += a[p] * w.z; acc[p][3] += a[p] * w.w;
            }
        }
        float4 bb = ld4(b1 + 4 * cg), gg = ld4(bng + 4 * cg), be = ld4(bnb + 4 * cg);
        float4 mm = ld4(bnm + 4 * cg), vv = ld4(bnv + 4 * cg);
        float4 sc, off;
        sc.x = gg.x * rsqrtf(vv.x + 1e-5f); off.x = be.x + (bb.x - mm.x) * sc.x;
        sc.y = gg.y * rsqrtf(vv.y + 1e-5f); off.y = be.y + (bb.y - mm.y) * sc.y;
        sc.z = gg.z * rsqrtf(vv.z + 1e-5f); off.z = be.z + (bb.z - mm.z) * sc.z;
        sc.w = gg.w * rsqrtf(vv.w + 1e-5f); off.w = be.w + (bb.w - mm.w) * sc.w;
        #pragma unroll
        for (int p = 0; p < 16; p++) {
            float4 h;
            h.x = fmaxf(acc[p][0] * sc.x + off.x, 0.f);
            h.y = fmaxf(acc[p][1] * sc.y + off.y, 0.f);
            h.z = fmaxf(acc[p][2] * sc.z + off.z, 0.f);
            h.w = fmaxf(acc[p][3] * sc.w + off.w, 0.f);
            st4(hs + (ng * 16 + p) * HID + 4 * cg, h);
        }
    }
    __syncthreads();

    // phase 2: GEMM 256 -> 128, fused bias + relu, write z
    {
        const int cg = t & 31;   // 32 col-groups of 4 -> 128 cols
        const int ng = t >> 5;   // 8 node-groups of 8
        float acc[8][4];
        #pragma unroll
        for (int p = 0; p < 8; p++) { acc[p][0] = acc[p][1] = acc[p][2] = acc[p][3] = 0.f; }
        const float* hrow = hs + ng * 8 * HID;
        #pragma unroll 2
        for (int k = 0; k < HID; k++) {
            float4 w = ld4(W2 + k * EMB + 4 * cg);
            #pragma unroll
            for (int p = 0; p < 8; p++) {
                float a = hrow[p * HID + k];
                acc[p][0] += a * w.x; acc[p][1] += a * w.y;
                acc[p][2] += a * w.z; acc[p][3] += a * w.w;
            }
        }
        float4 bb = ld4(b2 + 4 * cg);
        #pragma unroll
        for (int p = 0; p < 8; p++) {
            int node = nb0 + ng * 8 + p;
            if (node < N_NODES) {
                float4 r;
                r.x = fmaxf(acc[p][0] + bb.x, 0.f);
                r.y = fmaxf(acc[p][1] + bb.y, 0.f);
                r.z = fmaxf(acc[p][2] + bb.z, 0.f);
                r.w = fmaxf(acc[p][3] + bb.w, 0.f);
                st4(g_z + (size_t)node * EMB + 4 * cg, r);
            }
        }
    }
}

// ---------------------------------------------------------------------------
// Pair kernel: 64 pairs/block, 256 threads, 2 CTAs/SM.
//   gather src/dst embeddings into smem TRANSPOSED [128 emb][64 pairs]
//   GEMM1 514 -> 256 (single k-loop, 4 segments per k), relu -> smem s1
//   GEMM2 256 -> 128, relu
//   GEMM3 128 -> 1 via warp reduction, nan_to_num, write logits
// edge_pairs is int32 (JAX coerces int64 -> int32 without x64 mode).
// ---------------------------------------------------------------------------
__global__ __launch_bounds__(256, 2) void pair_kernel(
    const int* __restrict__ ep, const float* __restrict__ ldeg,
    const float* __restrict__ SW1, const float* __restrict__ Sb1,
    const float* __restrict__ SW2, const float* __restrict__ Sb2,
    const float* __restrict__ SW3, const float* __restrict__ Sb3,
    float* __restrict__ out)
{
    extern __shared__ float sm[];   // phase A: srcT|dstT (2 x 128x64), phase B: s1 (64x256)
    __shared__ int sidx[64], didx[64];
    __shared__ float sdeg[64], ddeg[64];
    float* srcT = sm;               // [128 emb][64 pairs]
    float* dstT = sm + EMB * 64;    // [128 emb][64 pairs]
    const int t = threadIdx.x;
    const int p0 = blockIdx.x * 64;

    if (t < 64) {
        int p = p0 + t;
        int si = 0, di = 0;
        float a = 0.f, b = 0.f;
        if (p < N_PAIRS) {
            si = ep[2 * (size_t)p];
            di = ep[2 * (size_t)p + 1];
            a = ldeg[si]; b = ldeg[di];
        }
        sidx[t] = si; didx[t] = di;
        sdeg[t] = a; ddeg[t] = b;
    }
    __syncthreads();

    // gather embeddings transposed (lane = pair -> conflict-free STS)
    {
        const int pp = t & 63;
        const size_t sbase = (size_t)sidx[pp] * EMB;
        const size_t dbase = (size_t)didx[pp] * EMB;
        #pragma unroll
        for (int it = 0; it < 8; it++) {
            int c4 = (t >> 6) + 4 * it;   // 0..31
            float4 v = ld4(g_z + sbase + 4 * c4);
            srcT[(4*c4+0)*64+pp] = v.x; srcT[(4*c4+1)*64+pp] = v.y;
            srcT[(4*c4+2)*64+pp] = v.z; srcT[(4*c4+3)*64+pp] = v.w;
            float4 u = ld4(g_z + dbase + 4 * c4);
            dstT[(4*c4+0)*64+pp] = u.x; dstT[(4*c4+1)*64+pp] = u.y;
            dstT[(4*c4+2)*64+pp] = u.z; dstT[(4*c4+3)*64+pp] = u.w;
        }
    }
    __syncthreads();

    // GEMM1: [64 x 514] @ [514 x 256] — one pass over k=0..127, all 4 segments
    const int cg = t & 63;   // cols 4*cg
    const int pg = t >> 6;   // pairs pg*16 ..
    float acc[16][4];
    #pragma unroll
    for (int p = 0; p < 16; p++) { acc[p][0] = acc[p][1] = acc[p][2] = acc[p][3] = 0.f; }
    {
        const float* scol = srcT + pg * 16;
        const float* dcol = dstT + pg * 16;
        const float* w0p = SW1 + 4 * cg;              // seg 0: src
        const float* w1p = SW1 + EMB * HID + 4 * cg;  // seg 1: dst
        const float* w2p = SW1 + 2 * EMB * HID + 4 * cg;
        const float* w3p = SW1 + 3 * EMB * HID + 4 * cg;
        for (int k = 0; k < EMB; k++) {
            float s[16], d[16];
            #pragma unroll
            for (int q = 0; q < 4; q++) {
                float4 v = ld4(scol + k * 64 + 4 * q);
                s[4*q] = v.x; s[4*q+1] = v.y; s[4*q+2] = v.z; s[4*q+3] = v.w;
                float4 u = ld4(dcol + k * 64 + 4 * q);
                d[4*q] = u.x; d[4*q+1] = u.y; d[4*q+2] = u.z; d[4*q+3] = u.w;
            }
            float4 w;
            w = ld4(w0p + k * HID);
            #pragma unroll
            for (int p = 0; p < 16; p++) {
                acc[p][0] += s[p] * w.x; acc[p][1] += s[p] * w.y;
                acc[p][2] += s[p] * w.z; acc[p][3] += s[p] * w.w;
            }
            w = ld4(w1p + k * HID);
            #pragma unroll
            for (int p = 0; p < 16; p++) {
                acc[p][0] += d[p] * w.x; acc[p][1] += d[p] * w.y;
                acc[p][2] += d[p] * w.z; acc[p][3] += d[p] * w.w;
            }
            w = ld4(w2p + k * HID);
            #pragma unroll
            for (int p = 0; p < 16; p++) {
                float pr = s[p] * d[p];
                acc[p][0] += pr * w.x; acc[p][1] += pr * w.y;
                acc[p][2] += pr * w.z; acc[p][3] += pr * w.w;
            }
            w = ld4(w3p + k * HID);
            #pragma unroll
            for (int p = 0; p < 16; p++) {
                float ad = fabsf(s[p] - d[p]);
                acc[p][0] += ad * w.x; acc[p][1] += ad * w.y;
                acc[p][2] += ad * w.z; acc[p][3] += ad * w.w;
            }
        }
    }
    {                                                   // seg 4: degrees (k=512,513)
        float4 wa = ld4(SW1 + 512 * HID + 4 * cg);
        float4 wb = ld4(SW1 + 513 * HID + 4 * cg);
        #pragma unroll
        for (int p = 0; p < 16; p++) {
            float a = sdeg[pg * 16 + p], b = ddeg[pg * 16 + p];
            acc[p][0] += a * wa.x + b * wb.x;
            acc[p][1] += a * wa.y + b * wb.y;
            acc[p][2] += a * wa.z + b * wb.z;
            acc[p][3] += a * wa.w + b * wb.w;
        }
    }
    float4 bb1 = ld4(Sb1 + 4 * cg);
    __syncthreads();   // all srcT/dstT reads complete before overwrite
    float* s1 = sm;    // 64 x 256 overlay
    #pragma unroll
    for (int p = 0; p < 16; p++) {
        float4 r;
        r.x = fmaxf(acc[p][0] + bb1.x, 0.f);
        r.y = fmaxf(acc[p][1] + bb1.y, 0.f);
        r.z = fmaxf(acc[p][2] + bb1.z, 0.f);
        r.w = fmaxf(acc[p][3] + bb1.w, 0.f);
        st4(s1 + (pg * 16 + p) * HID + 4 * cg, r);
    }
    __syncthreads();

    // GEMM2: [64 x 256] @ [256 x 128]
    const int cg2 = t & 31;  // cols 4*cg2
    const int pg2 = t >> 5;  // pairs pg2*8 ..
    float acc2[8][4];
    #pragma unroll
    for (int p = 0; p < 8; p++) { acc2[p][0] = acc2[p][1] = acc2[p][2] = acc2[p][3] = 0.f; }
    const float* s1row = s1 + pg2 * 8 * HID;
    #pragma unroll 2
    for (int k = 0; k < HID; k++) {
        float4 w = ld4(SW2 + k * EMB + 4 * cg2);
        #pragma unroll
        for (int p = 0; p < 8; p++) {
            float a = s1row[p * HID + k];
            acc2[p][0] += a * w.x; acc2[p][1] += a * w.y;
            acc2[p][2] += a * w.z; acc2[p][3] += a * w.w;
        }
    }
    float4 bb2 = ld4(Sb2 + 4 * cg2);
    float4 w3 = ld4(SW3 + 4 * cg2);

    // GEMM3: relu(s2) . SW3, reduced across the warp (lanes = 32 col-groups)
    float r[8];
    #pragma unroll
    for (int p = 0; p < 8; p++) {
        float v0 = fmaxf(acc2[p][0] + bb2.x, 0.f);
        float v1 = fmaxf(acc2[p][1] + bb2.y, 0.f);
        float v2 = fmaxf(acc2[p][2] + bb2.z, 0.f);
        float v3 = fmaxf(acc2[p][3] + bb2.w, 0.f);
        r[p] = v0 * w3.x + v1 * w3.y + v2 * w3.z + v3 * w3.w;
    }
    #pragma unroll
    for (int off = 16; off > 0; off >>= 1) {
        #pragma unroll
        for (int p = 0; p < 8; p++)
            r[p] += __shfl_xor_sync(0xffffffffu, r[p], off);
    }
    if ((t & 31) == 0) {
        float sb = Sb3[0];
        #pragma unroll
        for (int p = 0; p < 8; p++) {
            int pr = p0 + pg2 * 8 + p;
            if (pr < N_PAIRS) {
                float l = r[p] + sb;
                if (isnan(l)) l = 0.f;
                else if (isinf(l)) l = (l > 0.f) ? 20.f : -20.f;
                out[pr] = l;
            }
        }
    }
}

extern "C" void kernel_launch(void* const* d_in, const int* in_sizes, int n_in,
                              void* d_out, int out_size)
{
    const float* x    = (const float*)d_in[0];
    // d_in[1] = edge_index (unused by reference)
    const int*   ep   = (const int*)d_in[2];      // int32 (JAX default, no x64)
    const float* xm   = (const float*)d_in[3];
    const float* xsd  = (const float*)d_in[4];
    const float* ldeg = (const float*)d_in[5];
    const float* W1   = (const float*)d_in[6];
    const float* b1   = (const float*)d_in[7];
    const float* bng  = (const float*)d_in[8];
    const float* bnb  = (const float*)d_in[9];
    const float* bnm  = (const float*)d_in[10];
    const float* bnv  = (const float*)d_in[11];
    const float* W2   = (const float*)d_in[12];
    const float* b2   = (const float*)d_in[13];
    const float* SW1  = (const float*)d_in[14];
    const float* Sb1  = (const float*)d_in[15];
    const float* SW2  = (const float*)d_in[16];
    const float* Sb2  = (const float*)d_in[17];
    const float* SW3  = (const float*)d_in[18];
    const float* Sb3  = (const float*)d_in[19];
    float* out = (float*)d_out;

    cudaFuncSetAttribute(node_kernel, cudaFuncAttributeMaxDynamicSharedMemorySize, 98304);
    cudaFuncSetAttribute(pair_kernel, cudaFuncAttributeMaxDynamicSharedMemorySize, 65536);

    node_kernel<<<(N_NODES + 63) / 64, 256, 98304>>>(x, xm, xsd, W1, b1, bng, bnb, bnm, bnv, W2, b2);
    pair_kernel<<<(N_PAIRS + 63) / 64, 256, 65536>>>(ep, ldeg, SW1, Sb1, SW2, Sb2, SW3, Sb3, out);
}

// round 4
// speedup vs baseline: 1.6918x; 1.1963x over previous
#include <cuda_runtime.h>
#include <math.h>

#define N_NODES 100000
#define IN_CH 128
#define HID 256
#define EMB 128
#define N_PAIRS 500000

__device__ float g_z[(size_t)N_NODES * EMB];

__device__ __forceinline__ float4 ld4(const float* p) { return *reinterpret_cast<const float4*>(p); }
__device__ __forceinline__ void st4(float* p, float4 v) { *reinterpret_cast<float4*>(p) = v; }

typedef unsigned long long u64;

__device__ __forceinline__ u64 fma2(u64 a, u64 b, u64 c) {
    u64 d;
    asm("fma.rn.f32x2 %0, %1, %2, %3;" : "=l"(d) : "l"(a), "l"(b), "l"(c));
    return d;
}
__device__ __forceinline__ u64 mul2(u64 a, u64 b) {
    u64 d;
    asm("mul.rn.f32x2 %0, %1, %2;" : "=l"(d) : "l"(a), "l"(b));
    return d;
}
__device__ __forceinline__ u64 dup2(float f) {
    u64 d; unsigned u = __float_as_uint(f);
    asm("mov.b64 %0, {%1, %1};" : "=l"(d) : "r"(u));
    return d;
}
__device__ __forceinline__ float2 unpk(u64 v) {
    float2 r;
    asm("mov.b64 {%0, %1}, %2;" : "=f"(r.x), "=f"(r.y) : "l"(v));
    return r;
}

#define NEG1_2 0xBF800000BF800000ull
#define ABS_2  0x7FFFFFFF7FFFFFFFull

// ---------------------------------------------------------------------------
// Node kernel: 64 nodes/block, 256 threads, 2 CTAs/SM.
// ---------------------------------------------------------------------------
__global__ __launch_bounds__(256, 2) void node_kernel(
    const float* __restrict__ x, const float* __restrict__ xm, const float* __restrict__ xsd,
    const float* __restrict__ W1, const float* __restrict__ b1,
    const float* __restrict__ bng, const float* __restrict__ bnb,
    const float* __restrict__ bnm, const float* __restrict__ bnv,
    const float* __restrict__ W2, const float* __restrict__ b2)
{
    extern __shared__ float sm[];
    float* xsT = sm;                 // [128 ch][64 nodes]
    float* hs  = sm + IN_CH * 64;    // [64 nodes][256]
    const int t = threadIdx.x;
    const int nb0 = blockIdx.x * 64;

    // phase 0: load + nan_to_num + standardize + clip, store transposed
    {
        const int nn = t & 63;
        const int node = nb0 + nn;
        const bool ok = node < N_NODES;
        #pragma unroll
        for (int it = 0; it < 8; it++) {
            int c4 = (t >> 6) + 4 * it;
            float4 v = make_float4(0.f, 0.f, 0.f, 0.f);
            if (ok) v = ld4(x + (size_t)node * IN_CH + 4 * c4);
            float4 m = ld4(xm + 4 * c4), s = ld4(xsd + 4 * c4);
            float a;
            a = isfinite(v.x) ? v.x : 0.f; a = (a - m.x) / s.x; xsT[(4*c4+0)*64+nn] = fminf(fmaxf(a,-10.f),10.f);
            a = isfinite(v.y) ? v.y : 0.f; a = (a - m.y) / s.y; xsT[(4*c4+1)*64+nn] = fminf(fmaxf(a,-10.f),10.f);
            a = isfinite(v.z) ? v.z : 0.f; a = (a - m.z) / s.z; xsT[(4*c4+2)*64+nn] = fminf(fmaxf(a,-10.f),10.f);
            a = isfinite(v.w) ? v.w : 0.f; a = (a - m.w) / s.w; xsT[(4*c4+3)*64+nn] = fminf(fmaxf(a,-10.f),10.f);
        }
    }
    __syncthreads();

    // phase 1: GEMM 128 -> 256 with packed f32x2 FMA (pack over nodes)
    {
        const int cg = t & 63;   // 64 col-groups of 4 -> 256 cols
        const int ng = t >> 6;   // 4 node-groups of 16
        u64 acc[8][4];
        #pragma unroll
        for (int pp = 0; pp < 8; pp++) { acc[pp][0]=acc[pp][1]=acc[pp][2]=acc[pp][3]=0ull; }
        const float* xcol = xsT + ng * 16;
        #pragma unroll 2
        for (int k = 0; k < IN_CH; k++) {
            u64 a2[8];
            const ulonglong2* sp = reinterpret_cast<const ulonglong2*>(xcol + k * 64);
            #pragma unroll
            for (int q = 0; q < 4; q++) { ulonglong2 v = sp[q]; a2[2*q] = v.x; a2[2*q+1] = v.y; }
            float4 w = ld4(W1 + k * HID + 4 * cg);
            u64 wx = dup2(w.x), wy = dup2(w.y), wz = dup2(w.z), ww = dup2(w.w);
            #pragma unroll
            for (int pp = 0; pp < 8; pp++) {
                acc[pp][0] = fma2(a2[pp], wx, acc[pp][0]);
                acc[pp][1] = fma2(a2[pp], wy, acc[pp][1]);
                acc[pp][2] = fma2(a2[pp], wz, acc[pp][2]);
                acc[pp][3] = fma2(a2[pp], ww, acc[pp][3]);
            }
        }
        float4 bb = ld4(b1 + 4 * cg), gg = ld4(bng + 4 * cg), be = ld4(bnb + 4 * cg);
        float4 mm = ld4(bnm + 4 * cg), vv = ld4(bnv + 4 * cg);
        float4 sc, off;
        sc.x = gg.x * rsqrtf(vv.x + 1e-5f); off.x = be.x + (bb.x - mm.x) * sc.x;
        sc.y = gg.y * rsqrtf(vv.y + 1e-5f); off.y = be.y + (bb.y - mm.y) * sc.y;
        sc.z = gg.z * rsqrtf(vv.z + 1e-5f); off.z = be.z + (bb.z - mm.z) * sc.z;
        sc.w = gg.w * rsqrtf(vv.w + 1e-5f); off.w = be.w + (bb.w - mm.w) * sc.w;
        #pragma unroll
        for (int pp = 0; pp < 8; pp++) {
            float2 e0 = unpk(acc[pp][0]), e1 = unpk(acc[pp][1]);
            float2 e2 = unpk(acc[pp][2]), e3 = unpk(acc[pp][3]);
            float4 h0, h1;
            h0.x = fmaxf(e0.x * sc.x + off.x, 0.f); h1.x = fmaxf(e0.y * sc.x + off.x, 0.f);
            h0.y = fmaxf(e1.x * sc.y + off.y, 0.f); h1.y = fmaxf(e1.y * sc.y + off.y, 0.f);
            h0.z = fmaxf(e2.x * sc.z + off.z, 0.f); h1.z = fmaxf(e2.y * sc.z + off.z, 0.f);
            h0.w = fmaxf(e3.x * sc.w + off.w, 0.f); h1.w = fmaxf(e3.y * sc.w + off.w, 0.f);
            st4(hs + (ng * 16 + 2*pp + 0) * HID + 4 * cg, h0);
            st4(hs + (ng * 16 + 2*pp + 1) * HID + 4 * cg, h1);
        }
    }
    __syncthreads();

    // phase 2: GEMM 256 -> 128, packed over cols (weight pairs free from LDG)
    {
        const int cg = t & 31;   // 32 col-groups of 4 -> 128 cols
        const int ng = t >> 5;   // 8 node-groups of 8
        u64 acc[8][2];
        #pragma unroll
        for (int p = 0; p < 8; p++) { acc[p][0] = acc[p][1] = 0ull; }
        const float* hrow = hs + ng * 8 * HID;
        #pragma unroll 2
        for (int k = 0; k < HID; k++) {
            ulonglong2 wv = *reinterpret_cast<const ulonglong2*>(W2 + k * EMB + 4 * cg);
            #pragma unroll
            for (int p = 0; p < 8; p++) {
                u64 a = dup2(hrow[p * HID + k]);
                acc[p][0] = fma2(a, wv.x, acc[p][0]);
                acc[p][1] = fma2(a, wv.y, acc[p][1]);
            }
        }
        float4 bb = ld4(b2 + 4 * cg);
        #pragma unroll
        for (int p = 0; p < 8; p++) {
            int node = nb0 + ng * 8 + p;
            if (node < N_NODES) {
                float2 e0 = unpk(acc[p][0]), e1 = unpk(acc[p][1]);
                float4 r;
                r.x = fmaxf(e0.x + bb.x, 0.f);
                r.y = fmaxf(e0.y + bb.y, 0.f);
                r.z = fmaxf(e1.x + bb.z, 0.f);
                r.w = fmaxf(e1.y + bb.w, 0.f);
                st4(g_z + (size_t)node * EMB + 4 * cg, r);
            }
        }
    }
}

// ---------------------------------------------------------------------------
// Pair kernel: 64 pairs/block, 256 threads, 2 CTAs/SM. Packed f32x2 math.
// ---------------------------------------------------------------------------
__global__ __launch_bounds__(256, 2) void pair_kernel(
    const int* __restrict__ ep, const float* __restrict__ ldeg,
    const float* __restrict__ SW1, const float* __restrict__ Sb1,
    const float* __restrict__ SW2, const float* __restrict__ Sb2,
    const float* __restrict__ SW3, const float* __restrict__ Sb3,
    float* __restrict__ out)
{
    extern __shared__ float sm[];   // phase A: srcT|dstT (2 x 128x64), phase B: s1 (64x256)
    __shared__ int sidx[64], didx[64];
    __shared__ float sdeg[64], ddeg[64];
    float* srcT = sm;               // [128 emb][64 pairs]
    float* dstT = sm + EMB * 64;    // [128 emb][64 pairs]
    const int t = threadIdx.x;
    const int p0 = blockIdx.x * 64;

    if (t < 64) {
        int p = p0 + t;
        int si = 0, di = 0;
        float a = 0.f, b = 0.f;
        if (p < N_PAIRS) {
            si = ep[2 * (size_t)p];
            di = ep[2 * (size_t)p + 1];
            a = ldeg[si]; b = ldeg[di];
        }
        sidx[t] = si; didx[t] = di;
        sdeg[t] = a; ddeg[t] = b;
    }
    __syncthreads();

    // gather embeddings transposed (lane = pair -> conflict-free STS)
    {
        const int pp = t & 63;
        const size_t sbase = (size_t)sidx[pp] * EMB;
        const size_t dbase = (size_t)didx[pp] * EMB;
        #pragma unroll
        for (int it = 0; it < 8; it++) {
            int c4 = (t >> 6) + 4 * it;
            float4 v = ld4(g_z + sbase + 4 * c4);
            srcT[(4*c4+0)*64+pp] = v.x; srcT[(4*c4+1)*64+pp] = v.y;
            srcT[(4*c4+2)*64+pp] = v.z; srcT[(4*c4+3)*64+pp] = v.w;
            float4 u = ld4(g_z + dbase + 4 * c4);
            dstT[(4*c4+0)*64+pp] = u.x; dstT[(4*c4+1)*64+pp] = u.y;
            dstT[(4*c4+2)*64+pp] = u.z; dstT[(4*c4+3)*64+pp] = u.w;
        }
    }
    __syncthreads();

    // GEMM1: [64 x 514] @ [514 x 256] — packed f32x2, 4 segments per k
    const int cg = t & 63;   // cols 4*cg
    const int pg = t >> 6;   // pairs pg*16 ..
    u64 acc[8][4];
    #pragma unroll
    for (int pp = 0; pp < 8; pp++) { acc[pp][0]=acc[pp][1]=acc[pp][2]=acc[pp][3]=0ull; }
    {
        const float* scol = srcT + pg * 16;
        const float* dcol = dstT + pg * 16;
        const float* w0p = SW1 + 4 * cg;
        const float* w1p = SW1 + EMB * HID + 4 * cg;
        const float* w2p = SW1 + 2 * EMB * HID + 4 * cg;
        const float* w3p = SW1 + 3 * EMB * HID + 4 * cg;
        #pragma unroll 2
        for (int k = 0; k < EMB; k++) {
            u64 s2[8], d2[8];
            const ulonglong2* spv = reinterpret_cast<const ulonglong2*>(scol + k * 64);
            const ulonglong2* dpv = reinterpret_cast<const ulonglong2*>(dcol + k * 64);
            #pragma unroll
            for (int q = 0; q < 4; q++) {
                ulonglong2 v = spv[q]; s2[2*q] = v.x; s2[2*q+1] = v.y;
                ulonglong2 u = dpv[q]; d2[2*q] = u.x; d2[2*q+1] = u.y;
            }
            {   // seg 0: src
                float4 w = ld4(w0p + k * HID);
                u64 wx = dup2(w.x), wy = dup2(w.y), wz = dup2(w.z), ww = dup2(w.w);
                #pragma unroll
                for (int pp = 0; pp < 8; pp++) {
                    acc[pp][0] = fma2(s2[pp], wx, acc[pp][0]);
                    acc[pp][1] = fma2(s2[pp], wy, acc[pp][1]);
                    acc[pp][2] = fma2(s2[pp], wz, acc[pp][2]);
                    acc[pp][3] = fma2(s2[pp], ww, acc[pp][3]);
                }
            }
            {   // seg 1: dst
                float4 w = ld4(w1p + k * HID);
                u64 wx = dup2(w.x), wy = dup2(w.y), wz = dup2(w.z), ww = dup2(w.w);
                #pragma unroll
                for (int pp = 0; pp < 8; pp++) {
                    acc[pp][0] = fma2(d2[pp], wx, acc[pp][0]);
                    acc[pp][1] = fma2(d2[pp], wy, acc[pp][1]);
                    acc[pp][2] = fma2(d2[pp], wz, acc[pp][2]);
                    acc[pp][3] = fma2(d2[pp], ww, acc[pp][3]);
                }
            }
            {   // seg 2: src*dst
                float4 w = ld4(w2p + k * HID);
                u64 wx = dup2(w.x), wy = dup2(w.y), wz = dup2(w.z), ww = dup2(w.w);
                #pragma unroll
                for (int pp = 0; pp < 8; pp++) {
                    u64 pr = mul2(s2[pp], d2[pp]);
                    acc[pp][0] = fma2(pr, wx, acc[pp][0]);
                    acc[pp][1] = fma2(pr, wy, acc[pp][1]);
                    acc[pp][2] = fma2(pr, wz, acc[pp][2]);
                    acc[pp][3] = fma2(pr, ww, acc[pp][3]);
                }
            }
            {   // seg 3: |src-dst|  (diff via fma with -1, abs via 64-bit mask)
                float4 w = ld4(w3p + k * HID);
                u64 wx = dup2(w.x), wy = dup2(w.y), wz = dup2(w.z), ww = dup2(w.w);
                #pragma unroll
                for (int pp = 0; pp < 8; pp++) {
                    u64 df = fma2(d2[pp], NEG1_2, s2[pp]);
                    u64 ad = df & ABS_2;
                    acc[pp][0] = fma2(ad, wx, acc[pp][0]);
                    acc[pp][1] = fma2(ad, wy, acc[pp][1]);
                    acc[pp][2] = fma2(ad, wz, acc[pp][2]);
                    acc[pp][3] = fma2(ad, ww, acc[pp][3]);
                }
            }
        }
    }
    {   // seg 4: degrees (k=512,513), packed pairs loaded directly from smem
        float4 wa = ld4(SW1 + 512 * HID + 4 * cg);
        float4 wb = ld4(SW1 + 513 * HID + 4 * cg);
        u64 wax = dup2(wa.x), way = dup2(wa.y), waz = dup2(wa.z), waw = dup2(wa.w);
        u64 wbx = dup2(wb.x), wby = dup2(wb.y), wbz = dup2(wb.z), wbw = dup2(wb.w);
        const u64* sdp = reinterpret_cast<const u64*>(sdeg + pg * 16);
        const u64* ddp = reinterpret_cast<const u64*>(ddeg + pg * 16);
        #pragma unroll
        for (int pp = 0; pp < 8; pp++) {
            u64 a = sdp[pp], b = ddp[pp];
            acc[pp][0] = fma2(a, wax, fma2(b, wbx, acc[pp][0]));
            acc[pp][1] = fma2(a, way, fma2(b, wby, acc[pp][1]));
            acc[pp][2] = fma2(a, waz, fma2(b, wbz, acc[pp][2]));
            acc[pp][3] = fma2(a, waw, fma2(b, wbw, acc[pp][3]));
        }
    }
    float4 bb1 = ld4(Sb1 + 4 * cg);
    __syncthreads();   // all srcT/dstT reads complete before overwrite
    float* s1 = sm;    // 64 x 256 overlay
    #pragma unroll
    for (int pp = 0; pp < 8; pp++) {
        float2 e0 = unpk(acc[pp][0]), e1 = unpk(acc[pp][1]);
        float2 e2 = unpk(acc[pp][2]), e3 = unpk(acc[pp][3]);
        float4 r0, r1;
        r0.x = fmaxf(e0.x + bb1.x, 0.f); r1.x = fmaxf(e0.y + bb1.x, 0.f);
        r0.y = fmaxf(e1.x + bb1.y, 0.f); r1.y = fmaxf(e1.y + bb1.y, 0.f);
        r0.z = fmaxf(e2.x + bb1.z, 0.f); r1.z = fmaxf(e2.y + bb1.z, 0.f);
        r0.w = fmaxf(e3.x + bb1.w, 0.f); r1.w = fmaxf(e3.y + bb1.w, 0.f);
        st4(s1 + (pg * 16 + 2*pp + 0) * HID + 4 * cg, r0);
        st4(s1 + (pg * 16 + 2*pp + 1) * HID + 4 * cg, r1);
    }
    __syncthreads();

    // GEMM2: [64 x 256] @ [256 x 128] — packed over cols
    const int cg2 = t & 31;
    const int pg2 = t >> 5;
    u64 acc2[8][2];
    #pragma unroll
    for (int p = 0; p < 8; p++) { acc2[p][0] = acc2[p][1] = 0ull; }
    const float* s1row = s1 + pg2 * 8 * HID;
    #pragma unroll 2
    for (int k = 0; k < HID; k++) {
        ulonglong2 wv = *reinterpret_cast<const ulonglong2*>(SW2 + k * EMB + 4 * cg2);
        #pragma unroll
        for (int p = 0; p < 8; p++) {
            u64 a = dup2(s1row[p * HID + k]);
            acc2[p][0] = fma2(a, wv.x, acc2[p][0]);
            acc2[p][1] = fma2(a, wv.y, acc2[p][1]);
        }
    }
    float4 bb2 = ld4(Sb2 + 4 * cg2);
    float4 w3 = ld4(SW3 + 4 * cg2);

    // GEMM3: relu(s2) . SW3, reduced across the warp
    float r[8];
    #pragma unroll
    for (int p = 0; p < 8; p++) {
        float2 e0 = unpk(acc2[p][0]), e1 = unpk(acc2[p][1]);
        float v0 = fmaxf(e0.x + bb2.x, 0.f);
        float v1 = fmaxf(e0.y + bb2.y, 0.f);
        float v2 = fmaxf(e1.x + bb2.z, 0.f);
        float v3 = fmaxf(e1.y + bb2.w, 0.f);
        r[p] = v0 * w3.x + v1 * w3.y + v2 * w3.z + v3 * w3.w;
    }
    #pragma unroll
    for (int off = 16; off > 0; off >>= 1) {
        #pragma unroll
        for (int p = 0; p < 8; p++)
            r[p] += __shfl_xor_sync(0xffffffffu, r[p], off);
    }
    if ((t & 31) == 0) {
        float sb = Sb3[0];
        #pragma unroll
        for (int p = 0; p < 8; p++) {
            int pr = p0 + pg2 * 8 + p;
            if (pr < N_PAIRS) {
                float l = r[p] + sb;
                if (isnan(l)) l = 0.f;
                else if (isinf(l)) l = (l > 0.f) ? 20.f : -20.f;
                out[pr] = l;
            }
        }
    }
}

extern "C" void kernel_launch(void* const* d_in, const int* in_sizes, int n_in,
                              void* d_out, int out_size)
{
    const float* x    = (const float*)d_in[0];
    const int*   ep   = (const int*)d_in[2];
    const float* xm   = (const float*)d_in[3];
    const float* xsd  = (const float*)d_in[4];
    const float* ldeg = (const float*)d_in[5];
    const float* W1   = (const float*)d_in[6];
    const float* b1   = (const float*)d_in[7];
    const float* bng  = (const float*)d_in[8];
    const float* bnb  = (const float*)d_in[9];
    const float* bnm  = (const float*)d_in[10];
    const float* bnv  = (const float*)d_in[11];
    const float* W2   = (const float*)d_in[12];
    const float* b2   = (const float*)d_in[13];
    const float* SW1  = (const float*)d_in[14];
    const float* Sb1  = (const float*)d_in[15];
    const float* SW2  = (const float*)d_in[16];
    const float* Sb2  = (const float*)d_in[17];
    const float* SW3  = (const float*)d_in[18];
    const float* Sb3  = (const float*)d_in[19];
    float* out = (float*)d_out;

    cudaFuncSetAttribute(node_kernel, cudaFuncAttributeMaxDynamicSharedMemorySize, 98304);
    cudaFuncSetAttribute(pair_kernel, cudaFuncAttributeMaxDynamicSharedMemorySize, 65536);

    node_kernel<<<(N_NODES + 63) / 64, 256, 98304>>>(x, xm, xsd, W1, b1, bng, bnb, bnm, bnv, W2, b2);
    pair_kernel<<<(N_PAIRS + 63) / 64, 256, 65536>>>(ep, ldeg, SW1, Sb1, SW2, Sb2, SW3, Sb3, out);
}